// round 2
// baseline (speedup 1.0000x reference)
#include <cuda_runtime.h>
#include <cstdint>

// SNNController: T=1000, B=8192, I=9, H=96, O=3
// out[0 : T*B*O)           = spk2_rec (float)
// out[T*B*O : 2*T*B*O)     = mem2_rec (float)
//
// Parallelization: 8 lanes per batch element (G=8), each lane owns 12 hidden
// units. W1/W2 register-resident. Layer-1 and layer-2 math in packed f32x2
// (fma.rn.f32x2) to hit full fp32 rate on sm_103a. Reset term uses the
// identity rst_t == spk_{t-1}. One-step prefetch of x_{t+1}.
//
// R1 fix: epilogue lane guard was `else if (s < 7)` which let lane s==3 write
// outmem[-1] (previous batch's mem2[2]) -> mem2-only corruption, spk2 clean.

#define T_STEPS 1000
#define BATCH   8192
#define NIN     9
#define NH      96
#define NO      3
#define GSZ     8
#define HPL     12   // hidden units per lane
#define JP      6    // f32x2 pairs per lane

using ull = unsigned long long;

__device__ __forceinline__ ull pk2(float lo, float hi) {
    ull r; asm("mov.b64 %0, {%1, %2};" : "=l"(r) : "f"(lo), "f"(hi)); return r;
}
__device__ __forceinline__ float2 upk2(ull v) {
    float2 r; asm("mov.b64 {%0, %1}, %2;" : "=f"(r.x), "=f"(r.y) : "l"(v)); return r;
}
__device__ __forceinline__ ull ffma2(ull a, ull b, ull c) {
    ull d; asm("fma.rn.f32x2 %0, %1, %2, %3;" : "=l"(d) : "l"(a), "l"(b), "l"(c)); return d;
}
// (a > b) ? 1.0f : 0.0f  -- single FSET instruction
__device__ __forceinline__ float fsetgt(float a, float b) {
    float r; asm("set.gt.f32.f32 %0, %1, %2;" : "=f"(r) : "f"(a), "f"(b)); return r;
}

__global__ void __launch_bounds__(256, 1)
snn_kernel(const float* __restrict__ x,
           const float* __restrict__ W1, const float* __restrict__ b1,
           const float* __restrict__ W2, const float* __restrict__ b2,
           float* __restrict__ out)
{
    const int tid = blockIdx.x * blockDim.x + threadIdx.x;
    const int b   = tid >> 3;      // batch element
    const int s   = tid & 7;       // sublane within group of 8
    const int h0  = s * HPL;       // first hidden unit owned by this lane

    // ---- register-resident weights (packed over adjacent h) ----
    ull w1r[JP][NIN];
#pragma unroll
    for (int j = 0; j < JP; j++) {
        const int ha = h0 + 2 * j, hb = ha + 1;
#pragma unroll
        for (int i = 0; i < NIN; i++)
            w1r[j][i] = pk2(W1[ha * NIN + i], W1[hb * NIN + i]);
    }
    ull w2r[NO][JP];
#pragma unroll
    for (int o = 0; o < NO; o++) {
#pragma unroll
        for (int j = 0; j < JP; j++)
            w2r[o][j] = pk2(W2[o * NH + h0 + 2 * j], W2[o * NH + h0 + 2 * j + 1]);
    }
    ull b1p[JP];
#pragma unroll
    for (int j = 0; j < JP; j++)
        b1p[j] = pk2(b1[h0 + 2 * j], b1[h0 + 2 * j + 1]);
    const float b20 = b2[0], b21 = b2[1], b22 = b2[2];

    // ---- state ----
    ull m1[JP], s1[JP];                 // membrane-1 pairs, spike-1 pairs (0/1 floats)
#pragma unroll
    for (int j = 0; j < JP; j++) { m1[j] = 0ull; s1[j] = 0ull; }
    float mem20 = 0.f, mem21 = 0.f, mem22 = 0.f;
    float spk20 = 0.f, spk21 = 0.f, spk22 = 0.f;

    const ull BETA2 = pk2(0.92f, 0.92f);
    const ull NEG1  = pk2(-1.0f, -1.0f);

    const size_t xstride = (size_t)BATCH * NIN;
    const size_t ostride = (size_t)BATCH * NO;
    const float* xp = x + (size_t)b * NIN;
    float* outspk = out + (size_t)b * NO;
    float* outmem = out + (size_t)T_STEPS * BATCH * NO + (size_t)b * NO;

    // preload x(0)
    float xc[NIN];
#pragma unroll
    for (int i = 0; i < NIN; i++) xc[i] = xp[i];

    for (int t = 0; t < T_STEPS; t++) {
        // ---- prefetch x(t+1) ----
        float xn[NIN];
        const bool pf = (t + 1 < T_STEPS);
        const float* xpn = xp + xstride;
#pragma unroll
        for (int i = 0; i < NIN; i++) xn[i] = pf ? xpn[i] : 0.0f;

        // ---- layer 1: mem1 = 0.92*mem1 + (b1 - spk1_prev) + x @ W1^T ----
#pragma unroll
        for (int j = 0; j < JP; j++) {
            ull c = ffma2(s1[j], NEG1, b1p[j]);   // b1 - spk_prev (rst identity)
            m1[j] = ffma2(m1[j], BETA2, c);
        }
#pragma unroll
        for (int i = 0; i < NIN; i++) {
            const ull xx = pk2(xc[i], xc[i]);
#pragma unroll
            for (int j = 0; j < JP; j++)
                m1[j] = ffma2(xx, w1r[j][i], m1[j]);
        }
        // spike1 = (mem1 > 1)
#pragma unroll
        for (int j = 0; j < JP; j++) {
            float2 v = upk2(m1[j]);
            s1[j] = pk2(fsetgt(v.x, 1.0f), fsetgt(v.y, 1.0f));
        }

        // ---- layer 2 partials: cur2[o] = sum_h spk1[h]*W2[o][h] ----
        ull a0 = 0ull, a1 = 0ull, a2 = 0ull;
#pragma unroll
        for (int j = 0; j < JP; j++) {
            a0 = ffma2(s1[j], w2r[0][j], a0);
            a1 = ffma2(s1[j], w2r[1][j], a1);
            a2 = ffma2(s1[j], w2r[2][j], a2);
        }
        float2 v0 = upk2(a0), v1 = upk2(a1), v2 = upk2(a2);
        float c0 = v0.x + v0.y, c1 = v1.x + v1.y, c2 = v2.x + v2.y;
        // butterfly reduce over the 8 lanes of the group
#pragma unroll
        for (int d = 1; d < GSZ; d <<= 1) {
            c0 += __shfl_xor_sync(0xffffffffu, c0, d);
            c1 += __shfl_xor_sync(0xffffffffu, c1, d);
            c2 += __shfl_xor_sync(0xffffffffu, c2, d);
        }

        // ---- layer 2 membrane + spike (replicated in all lanes) ----
        mem20 = fmaf(mem20, 0.92f, c0 + fmaf(spk20, -1.0f, b20));
        mem21 = fmaf(mem21, 0.92f, c1 + fmaf(spk21, -1.0f, b21));
        mem22 = fmaf(mem22, 0.92f, c2 + fmaf(spk22, -1.0f, b22));
        spk20 = fsetgt(mem20, 1.0f);
        spk21 = fsetgt(mem21, 1.0f);
        spk22 = fsetgt(mem22, 1.0f);

        // ---- write outputs: lanes 0-2 -> spk2, lanes 4-6 -> mem2 ----
        if (s < 3) {
            float v = (s == 0) ? spk20 : ((s == 1) ? spk21 : spk22);
            outspk[s] = v;
        } else if (s >= 4 && s < 7) {
            float v = (s == 4) ? mem20 : ((s == 5) ? mem21 : mem22);
            outmem[s - 4] = v;
        }

        // advance
        xp += xstride;
        outspk += ostride;
        outmem += ostride;
#pragma unroll
        for (int i = 0; i < NIN; i++) xc[i] = xn[i];
    }
}

extern "C" void kernel_launch(void* const* d_in, const int* in_sizes, int n_in,
                              void* d_out, int out_size) {
    const float* x  = (const float*)d_in[0];
    const float* W1 = (const float*)d_in[1];
    const float* b1 = (const float*)d_in[2];
    const float* W2 = (const float*)d_in[3];
    const float* b2 = (const float*)d_in[4];
    float* out = (float*)d_out;

    const int threads = 256;
    const int total   = BATCH * GSZ;          // 65536 threads
    snn_kernel<<<total / threads, threads>>>(x, W1, b1, W2, b2, out);
}